// round 1
// baseline (speedup 1.0000x reference)
#include <cuda_runtime.h>
#include <cuda_bf16.h>
#include <mma.h>

using namespace nvcuda;

// Problem dims (fixed for this dataset)
#define MB   4096           // batch
#define HD   1024           // hidden = input size
#define NG   4096           // 4*H gate columns
#define KTOT 2048           // I + H concatenated K

// GEMM tiling
#define BM  128
#define BN  128
#define BK  32
#define PAD 4

// 64 MB scratch for the pre-activation gates [B, 4H] (device global: allowed scratch)
__device__ float g_gates[(size_t)MB * NG];

// ---------------------------------------------------------------------------
// GEMM: gates = [x|hx] @ [W_ih|W_hh]^T   (tf32 wmma, fp32 accumulate)
// A row-major [M, K], W row-major [N, K]  -> B is col-major KxN with ld = K.
// K-tiles never straddle the x/hx boundary (1024 % 32 == 0).
// ---------------------------------------------------------------------------
__global__ __launch_bounds__(256) void gates_gemm_tf32() {
    // bound device pointers via grid-constant-free approach: passed via
    // __device__ pointers set below (see launch). Instead we take them as
    // kernel params — declared here:
    // (real signature provided by wrapper below)
    // -- placeholder removed --
}

__global__ __launch_bounds__(256)
void gates_gemm(const float* __restrict__ x,
                const float* __restrict__ hx,
                const float* __restrict__ w_ih,
                const float* __restrict__ w_hh) {
    __shared__ __align__(16) float As[BM][BK + PAD];
    __shared__ __align__(16) float Ws[BN][BK + PAD];

    const int tid  = threadIdx.x;
    const int warp = tid >> 5;
    const int wm   = warp >> 2;   // 0..1 : warp row (64 rows each)
    const int wn   = warp & 3;    // 0..3 : warp col (32 cols each)

    const int block_m = blockIdx.y * BM;
    const int block_n = blockIdx.x * BN;

    wmma::fragment<wmma::accumulator, 16, 16, 8, float> acc[4][2];
    #pragma unroll
    for (int i = 0; i < 4; i++)
        #pragma unroll
        for (int j = 0; j < 2; j++)
            wmma::fill_fragment(acc[i][j], 0.0f);

    for (int k0 = 0; k0 < KTOT; k0 += BK) {
        const float* Aptr;
        const float* Wptr;
        int kk;
        if (k0 < HD) { Aptr = x;  Wptr = w_ih; kk = k0; }
        else         { Aptr = hx; Wptr = w_hh; kk = k0 - HD; }

        // Load A tile: 128 rows x 32 cols = 1024 float4, 4 per thread
        #pragma unroll
        for (int i = 0; i < 4; i++) {
            int f = tid + i * 256;
            int r = f >> 3;
            int c = (f & 7) << 2;
            float4 v = *reinterpret_cast<const float4*>(
                &Aptr[(size_t)(block_m + r) * HD + kk + c]);
            *reinterpret_cast<float4*>(&As[r][c]) = v;
        }
        // Load W tile (rows = gate-output n, cols = k)
        #pragma unroll
        for (int i = 0; i < 4; i++) {
            int f = tid + i * 256;
            int r = f >> 3;
            int c = (f & 7) << 2;
            float4 v = *reinterpret_cast<const float4*>(
                &Wptr[(size_t)(block_n + r) * HD + kk + c]);
            *reinterpret_cast<float4*>(&Ws[r][c]) = v;
        }
        __syncthreads();

        #pragma unroll
        for (int ks = 0; ks < BK; ks += 8) {
            wmma::fragment<wmma::matrix_a, 16, 16, 8, wmma::precision::tf32,
                           wmma::row_major> af[4];
            wmma::fragment<wmma::matrix_b, 16, 16, 8, wmma::precision::tf32,
                           wmma::col_major> bf[2];
            #pragma unroll
            for (int i = 0; i < 4; i++) {
                wmma::load_matrix_sync(af[i], &As[wm * 64 + i * 16][ks], BK + PAD);
                #pragma unroll
                for (int t = 0; t < af[i].num_elements; t++)
                    af[i].x[t] = wmma::__float_to_tf32(af[i].x[t]);
            }
            #pragma unroll
            for (int j = 0; j < 2; j++) {
                wmma::load_matrix_sync(bf[j], &Ws[wn * 32 + j * 16][ks], BK + PAD);
                #pragma unroll
                for (int t = 0; t < bf[j].num_elements; t++)
                    bf[j].x[t] = wmma::__float_to_tf32(bf[j].x[t]);
            }
            #pragma unroll
            for (int i = 0; i < 4; i++)
                #pragma unroll
                for (int j = 0; j < 2; j++)
                    wmma::mma_sync(acc[i][j], af[i], bf[j], acc[i][j]);
        }
        __syncthreads();
    }

    #pragma unroll
    for (int i = 0; i < 4; i++)
        #pragma unroll
        for (int j = 0; j < 2; j++) {
            float* out = &g_gates[(size_t)(block_m + wm * 64 + i * 16) * NG +
                                  block_n + wn * 32 + j * 16];
            wmma::store_matrix_sync(out, acc[i][j], NG, wmma::mem_row_major);
        }
}

// ---------------------------------------------------------------------------
// Elementwise LSTM epilogue with diagonal peepholes.
// NOTE: reference reuses W_peephole_f for the output gate — replicated here.
// out layout: [hy (B*H) | cy (B*H)]
// ---------------------------------------------------------------------------
__global__ __launch_bounds__(256)
void lstm_epilogue(const float* __restrict__ cx,
                   const float* __restrict__ b_ih,
                   const float* __restrict__ b_hh,
                   const float* __restrict__ wpi,
                   const float* __restrict__ wpf,
                   float* __restrict__ out) {
    int idx = blockIdx.x * blockDim.x + threadIdx.x;   // 0 .. B*H-1
    int b = idx >> 10;
    int h = idx & (HD - 1);

    const float* gr = g_gates + (size_t)b * NG;
    float ig = gr[h]           + b_ih[h]           + b_hh[h];
    float fg = gr[HD + h]      + b_ih[HD + h]      + b_hh[HD + h];
    float gg = gr[2 * HD + h]  + b_ih[2 * HD + h]  + b_hh[2 * HD + h];
    float og = gr[3 * HD + h]  + b_ih[3 * HD + h]  + b_hh[3 * HD + h];

    float c  = cx[idx];
    float pi = wpi[(size_t)h * (HD + 1)];   // diag element
    float pf = wpf[(size_t)h * (HD + 1)];

    float i_s = 1.0f / (1.0f + expf(-(ig + c * pi)));
    float f_s = 1.0f / (1.0f + expf(-(fg + c * pf)));
    float g_t = tanhf(gg);
    float cy  = f_s * c + i_s * g_t;
    float o_s = 1.0f / (1.0f + expf(-(og + cy * pf)));  // reuses pf (faithful)
    float hy  = o_s * tanhf(cy);

    out[idx] = hy;
    out[(size_t)MB * HD + idx] = cy;
}

extern "C" void kernel_launch(void* const* d_in, const int* in_sizes, int n_in,
                              void* d_out, int out_size) {
    const float* x    = (const float*)d_in[0];
    const float* hx   = (const float*)d_in[1];
    const float* cx   = (const float*)d_in[2];
    const float* w_ih = (const float*)d_in[3];
    const float* w_hh = (const float*)d_in[4];
    const float* b_ih = (const float*)d_in[5];
    const float* b_hh = (const float*)d_in[6];
    const float* wpi  = (const float*)d_in[7];
    const float* wpf  = (const float*)d_in[8];
    // d_in[9] (W_peephole_o) is unused: reference reuses W_peephole_f.
    float* out = (float*)d_out;

    dim3 grid(NG / BN, MB / BM);   // 32 x 32 CTAs
    gates_gemm<<<grid, 256>>>(x, hx, w_ih, w_hh);

    int total = MB * HD;
    lstm_epilogue<<<total / 256, 256>>>(cx, b_ih, b_hh, wpi, wpf, out);
}

// round 3
// speedup vs baseline: 4.0186x; 4.0186x over previous
#include <cuda_runtime.h>
#include <cuda_fp16.h>
#include <cstdint>

// ---------------------------------------------------------------------------
// LSTM cell w/ diagonal peepholes.
//   1) convert: x|hx -> g_A fp16 [4096x2048], W_ih|W_hh -> g_W fp16 [4096x2048]
//   2) GEMM: g_gates = A @ W^T  (mma.sync m16n8k16 fp16, fp32 acc,
//      4-stage cp.async pipeline, ldmatrix)
//   3) elementwise LSTM epilogue
// tcgen05 is unavailable (harness PTX targets plain sm_103, no 'a' features).
// ---------------------------------------------------------------------------

#define MB 4096
#define HD 1024
#define NG 4096
#define KT 2048

#define BM 128
#define BN 128
#define BKH 32              // K-halves per stage
#define NSTG 4
#define RSB 80              // smem row stride bytes (32 halves + 8 pad)
#define TILE_BYTES (BM * RSB)          // 10240
#define STG_BYTES  (2 * TILE_BYTES)    // 20480 (A then B)
#define SMEM_BYTES (NSTG * STG_BYTES)  // 81920

__device__ __half g_A[(size_t)MB * KT];
__device__ __half g_W[(size_t)NG * KT];
__device__ float  g_gates[(size_t)MB * NG];

// ----------------------------- helpers ------------------------------------
__device__ __forceinline__ uint32_t smem_u32(const void* p) {
    uint32_t a;
    asm("{ .reg .u64 t; cvta.to.shared.u64 t, %1; cvt.u32.u64 %0, t; }"
        : "=r"(a) : "l"(p));
    return a;
}
__device__ __forceinline__ void cp16(uint32_t dst, const void* src) {
    asm volatile("cp.async.cg.shared.global [%0], [%1], 16;"
                 :: "r"(dst), "l"(src) : "memory");
}
#define CP_COMMIT() asm volatile("cp.async.commit_group;" ::: "memory")
#define CP_WAIT2()  asm volatile("cp.async.wait_group 2;"  ::: "memory")

#define LDSM_X4(r0, r1, r2, r3, addr) \
    asm volatile("ldmatrix.sync.aligned.m8n8.x4.shared.b16 {%0,%1,%2,%3}, [%4];" \
                 : "=r"(r0), "=r"(r1), "=r"(r2), "=r"(r3) : "r"(addr))
#define LDSM_X2(r0, r1, addr) \
    asm volatile("ldmatrix.sync.aligned.m8n8.x2.shared.b16 {%0,%1}, [%2];" \
                 : "=r"(r0), "=r"(r1) : "r"(addr))

#define MMA16816(c, a, b) \
    asm volatile("mma.sync.aligned.m16n8k16.row.col.f32.f16.f16.f32 " \
                 "{%0,%1,%2,%3}, {%4,%5,%6,%7}, {%8,%9}, {%0,%1,%2,%3};" \
                 : "+f"((c)[0]), "+f"((c)[1]), "+f"((c)[2]), "+f"((c)[3]) \
                 : "r"((a)[0]), "r"((a)[1]), "r"((a)[2]), "r"((a)[3]), \
                   "r"((b)[0]), "r"((b)[1]))

// ----------------------------- convert ------------------------------------
__global__ __launch_bounds__(256)
void convert_f16(const float* __restrict__ x,  const float* __restrict__ hx,
                 const float* __restrict__ wih, const float* __restrict__ whh) {
    const size_t NA = (size_t)MB * KT / 4;   // 2M float4 for A, 2M for W
    size_t id = (size_t)blockIdx.x * blockDim.x + threadIdx.x;
    if (id < NA) {
        size_t m  = id >> 9;                 // 512 float4 per 2048-row
        size_t k4 = (id & 511) * 4;
        const float* src = (k4 < HD) ? (x + m * HD + k4)
                                     : (hx + m * HD + (k4 - HD));
        float4 v = *(const float4*)src;
        __half2* dst = (__half2*)(g_A + id * 4);
        dst[0] = __floats2half2_rn(v.x, v.y);
        dst[1] = __floats2half2_rn(v.z, v.w);
    } else if (id < 2 * NA) {
        size_t j  = id - NA;
        size_t n  = j >> 9;
        size_t k4 = (j & 511) * 4;
        const float* src = (k4 < HD) ? (wih + n * HD + k4)
                                     : (whh + n * HD + (k4 - HD));
        float4 v = *(const float4*)src;
        __half2* dst = (__half2*)(g_W + j * 4);
        dst[0] = __floats2half2_rn(v.x, v.y);
        dst[1] = __floats2half2_rn(v.z, v.w);
    }
}

// ----------------------------- GEMM ---------------------------------------
__global__ __launch_bounds__(256, 2)
void gates_gemm_f16() {
    extern __shared__ char smem[];
    const uint32_t sb = smem_u32(smem);

    const int tid  = threadIdx.x;
    const int lane = tid & 31;
    const int warp = tid >> 5;
    const int wm   = warp >> 2;          // 0..1 (64 rows each)
    const int wn   = warp & 3;           // 0..3 (32 cols each)
    const int bm   = blockIdx.y * BM;
    const int bn   = blockIdx.x * BN;

    // per-thread cp.async chunk coords (2 chunks A + 2 chunks B per stage)
    //   f = tid + i*256 : row = f>>2, 16B chunk c = f&3
    const int r0 = tid >> 2, c0 = tid & 3;
    const int r1 = (tid + 256) >> 2, c1 = (tid + 256) & 3;

    // ldmatrix per-lane byte offsets
    const uint32_t aoff = (uint32_t)(lane & 15) * RSB + (uint32_t)(lane >> 4) * 16;
    const uint32_t boff = (uint32_t)(lane & 7)  * RSB + (uint32_t)((lane >> 3) & 1) * 16;

#define FILL(s_, kt_) do {                                                      \
        const uint32_t sa_ = sb + (uint32_t)(s_) * STG_BYTES;                   \
        const __half* ga_ = g_A + (size_t)(bm) * KT + (size_t)(kt_) * BKH;      \
        const __half* gw_ = g_W + (size_t)(bn) * KT + (size_t)(kt_) * BKH;      \
        cp16(sa_ + (uint32_t)r0 * RSB + (uint32_t)c0 * 16, ga_ + (size_t)r0 * KT + c0 * 8); \
        cp16(sa_ + (uint32_t)r1 * RSB + (uint32_t)c1 * 16, ga_ + (size_t)r1 * KT + c1 * 8); \
        cp16(sa_ + TILE_BYTES + (uint32_t)r0 * RSB + (uint32_t)c0 * 16, gw_ + (size_t)r0 * KT + c0 * 8); \
        cp16(sa_ + TILE_BYTES + (uint32_t)r1 * RSB + (uint32_t)c1 * 16, gw_ + (size_t)r1 * KT + c1 * 8); \
    } while (0)

    FILL(0, 0); CP_COMMIT();
    FILL(1, 1); CP_COMMIT();
    FILL(2, 2); CP_COMMIT();

    float acc[4][4][4];
    #pragma unroll
    for (int i = 0; i < 4; i++)
        #pragma unroll
        for (int j = 0; j < 4; j++)
            #pragma unroll
            for (int e = 0; e < 4; e++) acc[i][j][e] = 0.0f;

    #pragma unroll 1
    for (int kt = 0; kt < KT / BKH; kt++) {
        const int s = kt & 3;
        CP_WAIT2();
        __syncthreads();
        // refill the stage consumed at kt-1 (protected by the barrier above)
        if (kt + 3 < KT / BKH) FILL((kt + 3) & 3, kt + 3);
        CP_COMMIT();

        const uint32_t sa = sb + (uint32_t)s * STG_BYTES;
        const uint32_t sw = sa + TILE_BYTES;
        #pragma unroll
        for (int ks = 0; ks < 2; ks++) {
            uint32_t a[4][4], b[4][2];
            #pragma unroll
            for (int mt = 0; mt < 4; mt++) {
                const uint32_t ad = sa + (uint32_t)(wm * 64 + mt * 16) * RSB
                                       + (uint32_t)ks * 32 + aoff;
                LDSM_X4(a[mt][0], a[mt][1], a[mt][2], a[mt][3], ad);
            }
            #pragma unroll
            for (int nt = 0; nt < 4; nt++) {
                const uint32_t bd = sw + (uint32_t)(wn * 32 + nt * 8) * RSB
                                       + (uint32_t)ks * 32 + boff;
                LDSM_X2(b[nt][0], b[nt][1], bd);
            }
            #pragma unroll
            for (int mt = 0; mt < 4; mt++)
                #pragma unroll
                for (int nt = 0; nt < 4; nt++)
                    MMA16816(acc[mt][nt], a[mt], b[nt]);
        }
    }
#undef FILL

    // store acc -> g_gates
    const int g  = lane >> 2;
    const int tc = lane & 3;
    #pragma unroll
    for (int mt = 0; mt < 4; mt++) {
        #pragma unroll
        for (int nt = 0; nt < 4; nt++) {
            const int row = bm + wm * 64 + mt * 16 + g;
            const int col = bn + wn * 32 + nt * 8 + tc * 2;
            float* p0 = g_gates + (size_t)row * NG + col;
            *(float2*)p0 = make_float2(acc[mt][nt][0], acc[mt][nt][1]);
            float* p1 = p0 + (size_t)8 * NG;
            *(float2*)p1 = make_float2(acc[mt][nt][2], acc[mt][nt][3]);
        }
    }
}

// ----------------------------- LSTM epilogue ------------------------------
__device__ __forceinline__ float sigmoidf_(float v) {
    return 1.0f / (1.0f + expf(-v));
}

__global__ __launch_bounds__(256)
void lstm_epilogue(const float* __restrict__ cx,
                   const float* __restrict__ b_ih,
                   const float* __restrict__ b_hh,
                   const float* __restrict__ wpi,
                   const float* __restrict__ wpf,
                   float* __restrict__ out) {
    int idx = blockIdx.x * blockDim.x + threadIdx.x;   // 0 .. B*H-1
    int b = idx >> 10;
    int h = idx & (HD - 1);

    const float* gr = g_gates + (size_t)b * NG;
    float ig = gr[h]          + b_ih[h]          + b_hh[h];
    float fg = gr[HD + h]     + b_ih[HD + h]     + b_hh[HD + h];
    float gg = gr[2 * HD + h] + b_ih[2 * HD + h] + b_hh[2 * HD + h];
    float og = gr[3 * HD + h] + b_ih[3 * HD + h] + b_hh[3 * HD + h];

    float c  = cx[idx];
    float pi = wpi[(size_t)h * (HD + 1)];
    float pf = wpf[(size_t)h * (HD + 1)];

    float i_s = sigmoidf_(ig + c * pi);
    float f_s = sigmoidf_(fg + c * pf);
    float g_t = tanhf(gg);
    float cy  = f_s * c + i_s * g_t;
    float o_s = sigmoidf_(og + cy * pf);   // reference reuses W_peephole_f
    float hy  = o_s * tanhf(cy);

    out[idx] = hy;
    out[(size_t)MB * HD + idx] = cy;
}

// ---------------------------------------------------------------------------
extern "C" void kernel_launch(void* const* d_in, const int* in_sizes, int n_in,
                              void* d_out, int out_size) {
    const float* x    = (const float*)d_in[0];
    const float* hx   = (const float*)d_in[1];
    const float* cx   = (const float*)d_in[2];
    const float* w_ih = (const float*)d_in[3];
    const float* w_hh = (const float*)d_in[4];
    const float* b_ih = (const float*)d_in[5];
    const float* b_hh = (const float*)d_in[6];
    const float* wpi  = (const float*)d_in[7];
    const float* wpf  = (const float*)d_in[8];
    // d_in[9] (W_peephole_o) unused: reference reuses W_peephole_f.
    float* out = (float*)d_out;

    // 1) fp32 -> fp16 concat conversion (4M float4 -> 16384 blocks)
    convert_f16<<<16384, 256>>>(x, hx, w_ih, w_hh);

    // 2) GEMM
    static int smem_set = 0;
    if (!smem_set) {
        cudaFuncSetAttribute(gates_gemm_f16,
                             cudaFuncAttributeMaxDynamicSharedMemorySize,
                             SMEM_BYTES);
        smem_set = 1;
    }
    dim3 grid(NG / BN, MB / BM);   // 32 x 32
    gates_gemm_f16<<<grid, 256, SMEM_BYTES>>>();

    // 3) epilogue
    lstm_epilogue<<<(MB * HD) / 256, 256>>>(cx, b_ih, b_hh, wpi, wpf, out);
}

// round 4
// speedup vs baseline: 4.8557x; 1.2083x over previous
#include <cuda_runtime.h>
#include <cuda_fp16.h>
#include <cstdint>

// ---------------------------------------------------------------------------
// LSTM cell w/ diagonal peepholes.
//   1) convert: x|hx -> g_A fp16 [4096x2048], W_ih|W_hh -> g_W fp16 [4096x2048]
//   2) GEMM: g_gates(fp16) = A @ W^T  (mma.sync m16n8k16, fp32 acc,
//      3-stage cp.async pipeline, BK=64, ldmatrix.x4 both operands)
//   3) vectorized elementwise LSTM epilogue
// tcgen05 unavailable (harness PTX targets plain sm_103, no 'a' features).
// ---------------------------------------------------------------------------

#define MB 4096
#define HD 1024
#define NG 4096
#define KT 2048

#define BM 128
#define BN 128
#define BKH 64              // K-halves per stage
#define NSTG 3
#define RSB 144             // smem row stride bytes (64 halves = 128B + 16 pad)
#define TILE_BYTES (BM * RSB)          // 18432
#define STG_BYTES  (2 * TILE_BYTES)    // 36864 (A then B)
#define SMEM_BYTES (NSTG * STG_BYTES)  // 110592

__device__ __half g_A[(size_t)MB * KT];
__device__ __half g_W[(size_t)NG * KT];
__device__ __half g_gates[(size_t)MB * NG];     // fp16 pre-activation gates

// ----------------------------- helpers ------------------------------------
__device__ __forceinline__ uint32_t smem_u32(const void* p) {
    uint32_t a;
    asm("{ .reg .u64 t; cvta.to.shared.u64 t, %1; cvt.u32.u64 %0, t; }"
        : "=r"(a) : "l"(p));
    return a;
}
__device__ __forceinline__ void cp16(uint32_t dst, const void* src) {
    asm volatile("cp.async.cg.shared.global [%0], [%1], 16;"
                 :: "r"(dst), "l"(src) : "memory");
}
#define CP_COMMIT() asm volatile("cp.async.commit_group;" ::: "memory")
#define CP_WAIT1()  asm volatile("cp.async.wait_group 1;"  ::: "memory")

#define LDSM_X4(r0, r1, r2, r3, addr) \
    asm volatile("ldmatrix.sync.aligned.m8n8.x4.shared.b16 {%0,%1,%2,%3}, [%4];" \
                 : "=r"(r0), "=r"(r1), "=r"(r2), "=r"(r3) : "r"(addr))

#define MMA16816(c, a, b) \
    asm volatile("mma.sync.aligned.m16n8k16.row.col.f32.f16.f16.f32 " \
                 "{%0,%1,%2,%3}, {%4,%5,%6,%7}, {%8,%9}, {%0,%1,%2,%3};" \
                 : "+f"((c)[0]), "+f"((c)[1]), "+f"((c)[2]), "+f"((c)[3]) \
                 : "r"((a)[0]), "r"((a)[1]), "r"((a)[2]), "r"((a)[3]), \
                   "r"((b)[0]), "r"((b)[1]))

// ----------------------------- convert ------------------------------------
__global__ __launch_bounds__(256)
void convert_f16(const float* __restrict__ x,  const float* __restrict__ hx,
                 const float* __restrict__ wih, const float* __restrict__ whh) {
    const size_t NA = (size_t)MB * KT / 4;   // 2M float4 for A, 2M for W
    size_t id = (size_t)blockIdx.x * blockDim.x + threadIdx.x;
    if (id < NA) {
        size_t m  = id >> 9;
        size_t k4 = (id & 511) * 4;
        const float* src = (k4 < HD) ? (x + m * HD + k4)
                                     : (hx + m * HD + (k4 - HD));
        float4 v = *(const float4*)src;
        __half2* dst = (__half2*)(g_A + id * 4);
        dst[0] = __floats2half2_rn(v.x, v.y);
        dst[1] = __floats2half2_rn(v.z, v.w);
    } else if (id < 2 * NA) {
        size_t j  = id - NA;
        size_t n  = j >> 9;
        size_t k4 = (j & 511) * 4;
        const float* src = (k4 < HD) ? (wih + n * HD + k4)
                                     : (whh + n * HD + (k4 - HD));
        float4 v = *(const float4*)src;
        __half2* dst = (__half2*)(g_W + j * 4);
        dst[0] = __floats2half2_rn(v.x, v.y);
        dst[1] = __floats2half2_rn(v.z, v.w);
    }
}

// ----------------------------- GEMM ---------------------------------------
__global__ __launch_bounds__(256, 2)
void gates_gemm_f16() {
    extern __shared__ char smem[];
    const uint32_t sb = smem_u32(smem);

    const int tid  = threadIdx.x;
    const int lane = tid & 31;
    const int warp = tid >> 5;
    const int wm   = warp >> 2;          // 0..1 (64 rows each)
    const int wn   = warp & 3;           // 0..3 (32 cols each)
    const int bm   = blockIdx.y * BM;
    const int bn   = blockIdx.x * BN;

    // cp.async: per stage 128 rows x 8 chunks(16B) for A and for B;
    // 256 threads -> 4 chunks each per tile. f = tid + i*256: row=f>>3, c=f&7
    // ldmatrix per-lane byte offsets (RSB=144 is conflict-free)
    const uint32_t aoff = (uint32_t)(lane & 15) * RSB + (uint32_t)(lane >> 4) * 16;
    const uint32_t boff = (uint32_t)(lane & 7) * RSB + (uint32_t)((lane >> 3) & 1) * 16
                        + (uint32_t)(lane >> 4) * (8 * RSB);

#define FILL(s_, kt_) do {                                                       \
        const uint32_t sa_ = sb + (uint32_t)(s_) * STG_BYTES;                    \
        const __half* ga_ = g_A + (size_t)(bm) * KT + (size_t)(kt_) * BKH;       \
        const __half* gw_ = g_W + (size_t)(bn) * KT + (size_t)(kt_) * BKH;       \
        _Pragma("unroll")                                                        \
        for (int i_ = 0; i_ < 4; i_++) {                                         \
            const int f_ = tid + i_ * 256;                                       \
            const int r_ = f_ >> 3, c_ = f_ & 7;                                 \
            cp16(sa_ + (uint32_t)r_ * RSB + (uint32_t)c_ * 16,                   \
                 ga_ + (size_t)r_ * KT + c_ * 8);                                \
            cp16(sa_ + TILE_BYTES + (uint32_t)r_ * RSB + (uint32_t)c_ * 16,      \
                 gw_ + (size_t)r_ * KT + c_ * 8);                                \
        }                                                                        \
    } while (0)

    FILL(0, 0); CP_COMMIT();
    FILL(1, 1); CP_COMMIT();

    float acc[4][4][4];
    #pragma unroll
    for (int i = 0; i < 4; i++)
        #pragma unroll
        for (int j = 0; j < 4; j++)
            #pragma unroll
            for (int e = 0; e < 4; e++) acc[i][j][e] = 0.0f;

    #pragma unroll 1
    for (int kt = 0; kt < KT / BKH; kt++) {       // 32 stages
        const int s = kt % 3;
        CP_WAIT1();
        __syncthreads();
        if (kt + 2 < KT / BKH) FILL((kt + 2) % 3, kt + 2);
        CP_COMMIT();

        const uint32_t sa = sb + (uint32_t)s * STG_BYTES;
        const uint32_t sw = sa + TILE_BYTES;
        #pragma unroll
        for (int ks = 0; ks < 4; ks++) {          // 16 halves each
            uint32_t a[4][4], b[4][2];
            #pragma unroll
            for (int mt = 0; mt < 4; mt++) {
                const uint32_t ad = sa + (uint32_t)(wm * 64 + mt * 16) * RSB
                                       + (uint32_t)ks * 32 + aoff;
                LDSM_X4(a[mt][0], a[mt][1], a[mt][2], a[mt][3], ad);
            }
            #pragma unroll
            for (int np = 0; np < 2; np++) {      // nt pairs {0,1},{2,3}
                const uint32_t bd = sw + (uint32_t)(wn * 32 + np * 16) * RSB
                                       + (uint32_t)ks * 32 + boff;
                LDSM_X4(b[np * 2][0], b[np * 2][1],
                        b[np * 2 + 1][0], b[np * 2 + 1][1], bd);
            }
            #pragma unroll
            for (int mt = 0; mt < 4; mt++)
                #pragma unroll
                for (int nt = 0; nt < 4; nt++)
                    MMA16816(acc[mt][nt], a[mt], b[nt]);
        }
    }
#undef FILL

    // store acc -> g_gates (fp16)
    const int g  = lane >> 2;
    const int tc = lane & 3;
    #pragma unroll
    for (int mt = 0; mt < 4; mt++) {
        #pragma unroll
        for (int nt = 0; nt < 4; nt++) {
            const int row = bm + wm * 64 + mt * 16 + g;
            const int col = bn + wn * 32 + nt * 8 + tc * 2;
            __half2* p0 = (__half2*)(g_gates + (size_t)row * NG + col);
            *p0 = __floats2half2_rn(acc[mt][nt][0], acc[mt][nt][1]);
            __half2* p1 = (__half2*)(g_gates + (size_t)(row + 8) * NG + col);
            *p1 = __floats2half2_rn(acc[mt][nt][2], acc[mt][nt][3]);
        }
    }
}

// ----------------------------- LSTM epilogue ------------------------------
__device__ __forceinline__ float sigmoidf_(float v) {
    return 1.0f / (1.0f + expf(-v));
}

__global__ __launch_bounds__(256)
void lstm_epilogue(const float* __restrict__ cx,
                   const float* __restrict__ b_ih,
                   const float* __restrict__ b_hh,
                   const float* __restrict__ wpi,
                   const float* __restrict__ wpf,
                   float* __restrict__ out) {
    const int idx4 = (blockIdx.x * 256 + threadIdx.x) * 4;  // 4 elems/thread
    const int b = idx4 >> 10;
    const int h = idx4 & (HD - 1);

    const __half* gr = g_gates + (size_t)b * NG;
    float ig[4], fg[4], gg[4], og[4];
    #pragma unroll
    for (int G = 0; G < 4; G++) {
        const uint2 raw = *(const uint2*)(gr + G * HD + h);
        const float2 lo = __half22float2(*(const __half2*)&raw.x);
        const float2 hi = __half22float2(*(const __half2*)&raw.y);
        float* dst = (G == 0) ? ig : (G == 1) ? fg : (G == 2) ? gg : og;
        dst[0] = lo.x; dst[1] = lo.y; dst[2] = hi.x; dst[3] = hi.y;
    }
    const float4 bi0 = *(const float4*)(b_ih + h);
    const float4 bh0 = *(const float4*)(b_hh + h);
    const float4 bi1 = *(const float4*)(b_ih + HD + h);
    const float4 bh1 = *(const float4*)(b_hh + HD + h);
    const float4 bi2 = *(const float4*)(b_ih + 2 * HD + h);
    const float4 bh2 = *(const float4*)(b_hh + 2 * HD + h);
    const float4 bi3 = *(const float4*)(b_ih + 3 * HD + h);
    const float4 bh3 = *(const float4*)(b_hh + 3 * HD + h);
    const float4 c4 = *(const float4*)(cx + idx4);

    const float bsi[4] = {bi0.x + bh0.x, bi0.y + bh0.y, bi0.z + bh0.z, bi0.w + bh0.w};
    const float bsf[4] = {bi1.x + bh1.x, bi1.y + bh1.y, bi1.z + bh1.z, bi1.w + bh1.w};
    const float bsg[4] = {bi2.x + bh2.x, bi2.y + bh2.y, bi2.z + bh2.z, bi2.w + bh2.w};
    const float bso[4] = {bi3.x + bh3.x, bi3.y + bh3.y, bi3.z + bh3.z, bi3.w + bh3.w};
    const float cv[4]  = {c4.x, c4.y, c4.z, c4.w};

    float hy[4], cy[4];
    #pragma unroll
    for (int e = 0; e < 4; e++) {
        const float pi = wpi[(size_t)(h + e) * (HD + 1)];
        const float pf = wpf[(size_t)(h + e) * (HD + 1)];
        const float c  = cv[e];
        const float i_s = sigmoidf_(ig[e] + bsi[e] + c * pi);
        const float f_s = sigmoidf_(fg[e] + bsf[e] + c * pf);
        const float g_t = tanhf(gg[e] + bsg[e]);
        const float cyv = f_s * c + i_s * g_t;
        const float o_s = sigmoidf_(og[e] + bso[e] + cyv * pf);  // ref reuses W_f
        hy[e] = o_s * tanhf(cyv);
        cy[e] = cyv;
    }
    *(float4*)(out + idx4) = make_float4(hy[0], hy[1], hy[2], hy[3]);
    *(float4*)(out + (size_t)MB * HD + idx4) = make_float4(cy[0], cy[1], cy[2], cy[3]);
}

// ---------------------------------------------------------------------------
extern "C" void kernel_launch(void* const* d_in, const int* in_sizes, int n_in,
                              void* d_out, int out_size) {
    const float* x    = (const float*)d_in[0];
    const float* hx   = (const float*)d_in[1];
    const float* cx   = (const float*)d_in[2];
    const float* w_ih = (const float*)d_in[3];
    const float* w_hh = (const float*)d_in[4];
    const float* b_ih = (const float*)d_in[5];
    const float* b_hh = (const float*)d_in[6];
    const float* wpi  = (const float*)d_in[7];
    const float* wpf  = (const float*)d_in[8];
    // d_in[9] (W_peephole_o) unused: reference reuses W_peephole_f.
    float* out = (float*)d_out;

    convert_f16<<<16384, 256>>>(x, hx, w_ih, w_hh);

    static int smem_set = 0;
    if (!smem_set) {
        cudaFuncSetAttribute(gates_gemm_f16,
                             cudaFuncAttributeMaxDynamicSharedMemorySize,
                             SMEM_BYTES);
        smem_set = 1;
    }
    dim3 grid(NG / BN, MB / BM);   // 32 x 32
    gates_gemm_f16<<<grid, 256, SMEM_BYTES>>>();

    lstm_epilogue<<<(MB * HD) / 1024, 256>>>(cx, b_ih, b_hh, wpi, wpf, out);
}